// round 13
// baseline (speedup 1.0000x reference)
#include <cuda_runtime.h>
#include <cstddef>

// Problem constants (bigram trie, fixed shapes from reference)
#define V_  32768
#define C_  32
#define B_  32
#define K_  (V_ * C_)        // 1048576 bigram nodes
#define X_  (K_ + 1)         // pointers length
#define G_  V_               // unigram count
#define U_  (V_ + 1)         // first bigram node index

// Fused fill + sparse override, warp-specialized + warp-0 speculative hist:
//  - grid = 1024 blocks (32 rows x 32 v-chunks), 256 threads, 1 float4/thread
//  - warp 0 issues idx and ALL S=4 hist candidates concurrently (3 extra
//    uniform LDGs per block — negligible), selects h, then loads backoff and
//    prefetches override operands. Barrier-1 release chain: 2 L2 latencies.
//  - warps 1..7: one float4 load, then wait at barrier 1.
//  - post-fill barrier 2 orders the single predicated override STG.
__global__ void __launch_bounds__(256) llm_fused_kernel(
    const int* __restrict__ hist,
    const int* __restrict__ idx,
    const int* __restrict__ pointers,
    const int* __restrict__ ids,
    const float* __restrict__ logs,
    float* __restrict__ out,
    int S)
{
    __shared__ float s_back;

    const int blk   = blockIdx.x;          // 0..1023
    const int b     = blk >> 5;            // row (32 chunks per row)
    const int chunk = blk & 31;
    const int tid   = threadIdx.x;
    const int v0    = chunk * 1024 + tid * 4;
    float* __restrict__ row = out + (size_t)b * V_;

    // Every thread: its own fill data, issued immediately.
    const float4 lv = *reinterpret_cast<const float4*>(logs + v0);

    bool  ov_do  = false;
    int   ov_tok = 0;
    float ov_lp  = 0.0f;
    if (tid < 32) {
        // Level 0: idx and all hist candidates in flight concurrently.
        const int idxv = __ldg(idx);
        int h;
        if (S == 4) {
            const int a0 = __ldg(hist + 0 * B_ + b);
            const int a1 = __ldg(hist + 1 * B_ + b);
            const int a2 = __ldg(hist + 2 * B_ + b);
            const int a3 = __ldg(hist + 3 * B_ + b);
            const int sel = idxv - 1;
            h = (sel == 0) ? a0 : (sel == 1) ? a1 : (sel == 2) ? a2 : a3;
        } else {
            h = __ldg(hist + (idxv - 1) * B_ + b);
        }

        // Level 1 (mutually independent): backoff + child pointers.
        if (tid == 0)
            s_back = __ldg(logs + (size_t)X_ + G_ + h);
        const int off = __ldg(pointers + h);
        const int nc  = __ldg(pointers + h + 1) - off + 1;
        if (tid < nc) {
            const int node = h + off + tid;            // bigram node id
            ov_tok = __ldg(ids + (node - U_));         // child token id
            ov_lp  = __ldg(logs + node);               // bigram log-prob
            ov_do  = (ov_tok >> 10) == chunk;          // in this block's window
        }
    }

    __syncthreads();   // releases once s_back is written (2 L2 latencies + select)

    const float backoff = s_back;
    float4 o;
    o.x = backoff + lv.x;
    o.y = backoff + lv.y;
    o.z = backoff + lv.z;
    o.w = backoff + lv.w;
    *reinterpret_cast<float4*>(row + v0) = o;

    __syncthreads();   // fill stores ordered before overrides

    if (ov_do)
        row[ov_tok] = ov_lp;
}

extern "C" void kernel_launch(void* const* d_in, const int* in_sizes, int n_in,
                              void* d_out, int out_size)
{
    const int*   hist     = (const int*)d_in[0];   // (S, B) int32
    const int*   idx      = (const int*)d_in[1];   // scalar int32
    const int*   pointers = (const int*)d_in[2];   // (X,) int32
    const int*   ids      = (const int*)d_in[3];   // (K,) int32
    const float* logs     = (const float*)d_in[4]; // (L,) float32
    float*       out      = (float*)d_out;         // (B, V) float32

    const int S = in_sizes[0] / B_;                // history length (4)
    (void)n_in; (void)out_size;

    llm_fused_kernel<<<(B_ * V_) / (256 * 4), 256>>>(hist, idx, pointers, ids, logs, out, S);
}